// round 9
// baseline (speedup 1.0000x reference)
#include <cuda_runtime.h>
#include <cstdint>

// AtomicConv: E=640000, N=20000, K=16, T=8.
//
// Semantics (raw (K,E,1)->(E,K) reshape in the reference):
//   edge e: kp = e/40000 (one radial triple), distances d[16*(e%40000)+k]
//   out[dst[e], ti*16+k] += exp(-s(d-m)^2) * 0.5*(cos(pi*d/c)+1)*[d<=c]
//   ti = index of feat[src[e]] in features_to_use (miss -> skip edge)
//
// R9: warp-compacted scatter (R8) + instruction diet:
//   * cutoff select removed: 0.5*(cos(min(pi*d/c, pi))+1) == where(d<=c,...)
//   * -scl*log2e folded -> raw ex2.approx
//   * f32x2 packed math for dm, dm^2, arg, cos-arg
//   * packed {x,x} params in smem (LDS.64)
//   * 1-deep software pipelined drain loop

#define K_RADIAL 16
#define N_TYPES  8
#define E_PER_K  40000
#define PI_F     3.14159265358979323846f
#define LOG2E_F  1.4426950408889634f

typedef unsigned long long u64;

__device__ __forceinline__ u64 f2_add(u64 a, u64 b) {
    u64 r; asm("add.rn.f32x2 %0, %1, %2;" : "=l"(r) : "l"(a), "l"(b)); return r;
}
__device__ __forceinline__ u64 f2_mul(u64 a, u64 b) {
    u64 r; asm("mul.rn.f32x2 %0, %1, %2;" : "=l"(r) : "l"(a), "l"(b)); return r;
}
__device__ __forceinline__ void f2_unpack(u64 v, float& lo, float& hi) {
    asm("mov.b64 {%0, %1}, %2;" : "=f"(lo), "=f"(hi) : "l"(v));
}
__device__ __forceinline__ float fast_ex2(float x) {
    float r; asm("ex2.approx.f32 %0, %1;" : "=f"(r) : "f"(x)); return r;
}
__device__ __forceinline__ float fast_cos(float x) {
    float r; asm("cos.approx.f32 %0, %1;" : "=f"(r) : "f"(x)); return r;
}

__global__ void __launch_bounds__(256)
atomic_conv_warpc_kernel(const float* __restrict__ feat,
                         const float* __restrict__ dist,
                         const float* __restrict__ rparams,   // (K,3)
                         const float* __restrict__ ftu,       // (T,)
                         const int*   __restrict__ src,
                         const int*   __restrict__ dst,
                         float*       __restrict__ out,       // (N,T*K), zeroed
                         int n_edges)
{
    __shared__ u64  s_mneg[K_RADIAL];   // {-mean, -mean}
    __shared__ u64  s_nscl[K_RADIAL];   // {-scl*log2e, -scl*log2e}
    __shared__ u64  s_pic [K_RADIAL];   // {pi/cut, pi/cut}
    __shared__ int  s_tbl[32];          // atomic-number -> type index (-1)
    __shared__ int2 s_wl[8][32];        // per-warp worklist {off|kp<<24, em}

    const int tid = threadIdx.x;
    if (tid < 32) s_tbl[tid] = -1;
    if (tid < K_RADIAL) {
        const float c  = rparams[tid * 3 + 0];
        const float m  = rparams[tid * 3 + 1];
        const float s  = rparams[tid * 3 + 2];
        float2 t;
        t.x = t.y = -m;                 *(float2*)&s_mneg[tid] = t;
        t.x = t.y = -s * LOG2E_F;       *(float2*)&s_nscl[tid] = t;
        t.x = t.y = PI_F / c;           *(float2*)&s_pic [tid] = t;
    }
    __syncthreads();
    if (tid < N_TYPES) s_tbl[((int)ftu[tid]) & 31] = tid;
    __syncthreads();

    const int warp = tid >> 5;
    const int lane = tid & 31;
    const int e    = blockIdx.x * blockDim.x + tid;

    // ---- phase 1: scalar per-edge work (once per edge) ----
    int ti = -1, dn = 0;
    if (e < n_edges) {
        const int sn = src[e];
        dn = dst[e];
        const float f = __ldg(&feat[sn]);
        ti = s_tbl[((int)f) & 31];
    }
    const unsigned mask = __ballot_sync(0xFFFFFFFF, ti >= 0);
    const int nact = __popc(mask);
    if (ti >= 0) {
        const int cidx = __popc(mask & ((1u << lane) - 1u));
        const unsigned kp = (unsigned)e / E_PER_K;
        const int em = e - (int)(kp * E_PER_K);
        s_wl[warp][cidx] = make_int2(dn * (N_TYPES * K_RADIAL) + ti * K_RADIAL
                                     + (int)(kp << 24), em);
    }
    __syncwarp();

    // ---- phase 2: cooperative drain, 4 lanes per edge, 1-deep pipeline ----
    const int sub = lane >> 2;   // which of 8 edges this lane serves
    const int k4  = lane & 3;    // which k-quad this lane owns

    int idx = sub;
    bool valid = idx < nact;
    int2 w;  ulonglong2 dq;
    if (valid) {
        w  = s_wl[warp][idx];
        dq = __ldg((const ulonglong2*)dist + w.y * 4 + k4);
    }

    while (true) {
        // prefetch next iteration
        const int nidx = idx + 8;
        const bool nvalid = nidx < nact;
        int2 wn;  ulonglong2 dqn;
        if (nvalid) {
            wn  = s_wl[warp][nidx];
            dqn = __ldg((const ulonglong2*)dist + wn.y * 4 + k4);
        }

        if (valid) {
            const int kp  = (int)((unsigned)w.x >> 24);
            const int off = w.x & 0x00FFFFFF;

            const u64 mneg = s_mneg[kp];
            const u64 nscl = s_nscl[kp];
            const u64 pic  = s_pic [kp];

            // dm = d + (-mean); arg = (dm*dm) * (-scl*log2e)
            const u64 dm01 = f2_add(dq.x, mneg);
            const u64 dm23 = f2_add(dq.y, mneg);
            const u64 a01  = f2_mul(f2_mul(dm01, dm01), nscl);
            const u64 a23  = f2_mul(f2_mul(dm23, dm23), nscl);
            // cos arg = min(pic*d, pi)  (clamp == cutoff where())
            const u64 c01  = f2_mul(dq.x, pic);
            const u64 c23  = f2_mul(dq.y, pic);

            float a0, a1, a2, a3, t0, t1, t2, t3;
            f2_unpack(a01, a0, a1);  f2_unpack(a23, a2, a3);
            f2_unpack(c01, t0, t1);  f2_unpack(c23, t2, t3);

            const float r0 = fast_ex2(a0), r1 = fast_ex2(a1);
            const float r2 = fast_ex2(a2), r3 = fast_ex2(a3);

            const float w0 = fast_cos(fminf(t0, PI_F));
            const float w1 = fast_cos(fminf(t1, PI_F));
            const float w2 = fast_cos(fminf(t2, PI_F));
            const float w3 = fast_cos(fminf(t3, PI_F));

            const float v0 = r0 * fmaf(0.5f, w0, 0.5f);
            const float v1 = r1 * fmaf(0.5f, w1, 0.5f);
            const float v2 = r2 * fmaf(0.5f, w2, 0.5f);
            const float v3 = r3 * fmaf(0.5f, w3, 0.5f);

            float* addr = out + off + k4 * 4;
            asm volatile("red.global.add.v4.f32 [%0], {%1, %2, %3, %4};"
                         :: "l"(addr), "f"(v0), "f"(v1), "f"(v2), "f"(v3)
                         : "memory");
        }

        if (!nvalid) break;
        idx = nidx;  w = wn;  dq = dqn;  valid = true;
    }
}

extern "C" void kernel_launch(void* const* d_in, const int* in_sizes, int n_in,
                              void* d_out, int out_size)
{
    const float* feat    = (const float*)d_in[0];   // (N,1)
    const float* dist    = (const float*)d_in[1];   // (E,1)
    const float* rparams = (const float*)d_in[2];   // (K,3)
    const float* ftu     = (const float*)d_in[3];   // (T,)
    const int*   src     = (const int*)d_in[4];     // (E,)
    const int*   dst     = (const int*)d_in[5];     // (E,)
    float*       out     = (float*)d_out;           // (N, T*K)

    const int n_edges = in_sizes[1];

    cudaMemsetAsync(out, 0, (size_t)out_size * sizeof(float), 0);

    const int threads = 256;
    const int blocks  = (n_edges + threads - 1) / threads;
    atomic_conv_warpc_kernel<<<blocks, threads>>>(feat, dist, rparams, ftu,
                                                  src, dst, out, n_edges);
}